// round 5
// baseline (speedup 1.0000x reference)
#include <cuda_runtime.h>

#define N_NODES 20000
#define N_TOT   40000            // both graphs merged
#define N_EDGES 320000
#define E_TOT   640000
#define IN_DIM  128
#define HID     256
#define NL      3
#define NUM_ET  16
#define ETD     32
#define LN_EPS  1e-5f
#define NPART   100              // partials per graph for column mean

typedef unsigned long long u64;

// ---------------- scratch (device globals; no allocation allowed) ----------------
__device__ float g_h  [N_TOT * HID];
__device__ float g_Hm [N_TOT * HID];
__device__ float g_agg[N_TOT * HID];
__device__ int   g_cnt[N_TOT];
__device__ int   g_cur[N_TOT];
__device__ int   g_rs [N_TOT + 1];
__device__ int   g_csrc[E_TOT];
__device__ int   g_cet [E_TOT];
__device__ float g_etb [NL * NUM_ET * HID];
__device__ float g_part[2 * NPART * HID];

// ---------------- f32x2 packed-math helpers (sm_10x) ----------------
__device__ __forceinline__ void unpack2(u64 v, float& x, float& y) {
    asm("mov.b64 {%0, %1}, %2;" : "=f"(x), "=f"(y) : "l"(v));
}
__device__ __forceinline__ void fma2(u64& d, u64 a, u64 b) {
    asm("fma.rn.f32x2 %0, %1, %2, %0;" : "+l"(d) : "l"(a), "l"(b));
}

// ---------------- etb[l][t][o] = edge_embs[l][t] @ We[l]^T + b_msg[l] ----------------
__global__ void etb_kernel(const float* __restrict__ eemb,
                           const float* __restrict__ Wmsg,
                           const float* __restrict__ bmsg) {
    int idx = blockIdx.x * blockDim.x + threadIdx.x;
    if (idx >= NL * NUM_ET * HID) return;
    int o = idx % HID;
    int t = (idx / HID) % NUM_ET;
    int l = idx / (HID * NUM_ET);
    const float* e = eemb + (l * NUM_ET + t) * ETD;
    const float* w = Wmsg + (l * HID + o) * (HID + ETD) + HID;
    float s = bmsg[l * HID + o];
#pragma unroll
    for (int j = 0; j < ETD; j++) s = fmaf(e[j], w[j], s);
    g_etb[idx] = s;
}

// ---------------- merged CSR build over both graphs ----------------
__global__ void zero_counts_kernel() {
    int i = blockIdx.x * blockDim.x + threadIdx.x;
    if (i < N_TOT) { g_cnt[i] = 0; g_cur[i] = 0; }
}

__global__ void hist_kernel(const int* __restrict__ dst_a,
                            const int* __restrict__ dst_b) {
    int e = blockIdx.x * blockDim.x + threadIdx.x;
    if (e >= E_TOT) return;
    int d = (e < N_EDGES) ? dst_a[e] : (dst_b[e - N_EDGES] + N_NODES);
    atomicAdd(&g_cnt[d], 1);
}

// single-block exclusive scan over 40000 counts
__global__ void scan_kernel() {
    __shared__ int ps[1024];
    const int t = threadIdx.x;
    const int C = (N_TOT + 1023) / 1024;   // 40
    int base = t * C;
    int s = 0;
    for (int i = 0; i < C; i++) {
        int idx = base + i;
        if (idx < N_TOT) s += g_cnt[idx];
    }
    ps[t] = s;
    __syncthreads();
    for (int off = 1; off < 1024; off <<= 1) {
        int v = (t >= off) ? ps[t - off] : 0;
        __syncthreads();
        ps[t] += v;
        __syncthreads();
    }
    int run = (t > 0) ? ps[t - 1] : 0;
    for (int i = 0; i < C; i++) {
        int idx = base + i;
        if (idx < N_TOT) { g_rs[idx] = run; run += g_cnt[idx]; }
    }
    if (t == 1023) g_rs[N_TOT] = ps[1023];
}

__global__ void scatter_kernel(const int* __restrict__ src_a,
                               const int* __restrict__ dst_a,
                               const int* __restrict__ et_a,
                               const int* __restrict__ src_b,
                               const int* __restrict__ dst_b,
                               const int* __restrict__ et_b) {
    int e = blockIdx.x * blockDim.x + threadIdx.x;
    if (e >= E_TOT) return;
    int s, d, t;
    if (e < N_EDGES) {
        s = src_a[e];            d = dst_a[e];            t = et_a[e];
    } else {
        int eb = e - N_EDGES;
        s = src_b[eb] + N_NODES; d = dst_b[eb] + N_NODES; t = et_b[eb];
    }
    int p = g_rs[d] + atomicAdd(&g_cur[d], 1);
    g_csrc[p] = s;
    g_cet[p]  = t;
}

// ---------------- edge aggregation (gather-style, float4, no atomics) --------
// agg[n][:] = ( sum_{e in-edges of n} relu(Hm[src_e] + etb[l][et_e]) ) / max(deg,1)
__global__ void agg_kernel(int layer) {
    int n  = blockIdx.x;
    int c4 = threadIdx.x;                               // 0..63
    const float4* __restrict__ Hm4  = (const float4*)g_Hm;
    const float4* __restrict__ et4  = (const float4*)(g_etb + layer * NUM_ET * HID);
    int beg = g_rs[n], end = g_rs[n + 1];
    float4 acc = make_float4(0.f, 0.f, 0.f, 0.f);
    for (int i = beg; i < end; i++) {
        int s = g_csrc[i];
        int t = g_cet[i];
        float4 hv = Hm4[s * (HID / 4) + c4];
        float4 ev = __ldg(&et4[t * (HID / 4) + c4]);
        acc.x += fmaxf(hv.x + ev.x, 0.f);
        acc.y += fmaxf(hv.y + ev.y, 0.f);
        acc.z += fmaxf(hv.z + ev.z, 0.f);
        acc.w += fmaxf(hv.w + ev.w, 0.f);
    }
    float inv = 1.f / fmaxf((float)(end - beg), 1.f);
    acc.x *= inv; acc.y *= inv; acc.z *= inv; acc.w *= inv;
    ((float4*)g_agg)[n * (HID / 4) + c4] = acc;
}

// ---------------- column-mean partials (both graphs, deterministic) ----------
__global__ void colmean_kernel() {
    int c = threadIdx.x;                    // 256
    const int rows_per = N_TOT / (2 * NPART);   // 200
    int r0 = blockIdx.x * rows_per;
    int r1 = r0 + rows_per;
    float acc = 0.f;
    for (int r = r0; r < r1; r++) acc += g_h[r * HID + c];
    g_part[blockIdx.x * HID + c] = acc;
}

// ---------------- fused GEMM: C[M,256] = A[M,K] @ B[256,K]^T (+ epilogue) ----
// Double-buffered smem pipeline, one barrier per K-tile.
// A tile stored DUPLICATED in smem: As2[k][2m]=As2[k][2m+1]=A[m][k], so the
// (a,a) f32x2 operand pairs come straight out of LDS (no register packing MOVs).
// A is split across two base pointers at row `asplit` (graph a / graph b).
// EPI 0: C = acc
// EPI 1: C = relu(acc + bias)
// EPI 2: C = LayerNorm(acc + bias + resid; gamma, beta)
template <int KDIM, int EPI>
__global__ void __launch_bounds__(256, 3)
gemm_kernel(const float* __restrict__ A_a, const float* __restrict__ A_b,
            int asplit, int lda,
            const float* __restrict__ B, int ldb,
            const float* __restrict__ bias,
            const float* __restrict__ resid,
            const float* __restrict__ gamma,
            const float* __restrict__ beta,
            float* __restrict__ C) {
    constexpr int BM = 32, BK = 16;
    constexpr int NT = KDIM / BK;          // K-tiles
    __shared__ float As2[2][BK][BM * 2];   // duplicated pairs
    __shared__ float Bs [2][BK][256];

    const int t    = threadIdx.x;
    const int tcol = t & 31;       // lane: 32 col-groups
    const int trow = t >> 5;       // warp: 8 row-groups
    const int m0   = blockIdx.x * BM;

    const float* A = A_a;
    int am0 = m0;
    if (am0 >= asplit) { A = A_b; am0 -= asplit; }

    // per-thread load coordinates (constant across tiles)
    const int a_m  = (t & 127) >> 2;
    const int a_kq = (t & 3) * 4;
    const float* Arow = &A[(am0 + a_m) * lda + a_kq];
    const float* Brow = &B[t * ldb];

    // packed accumulators: acc2[r][p] = (C[m+r][c+2p], C[m+r][c+2p+1])
    u64 acc2[4][4];
#pragma unroll
    for (int r = 0; r < 4; r++)
#pragma unroll
        for (int p = 0; p < 4; p++) acc2[r][p] = 0ull;

    // ---- prologue: fill buffer 0 with tile 0 ----
    if (t < 128) {
        float4 v = *reinterpret_cast<const float4*>(Arow);
        *reinterpret_cast<float2*>(&As2[0][a_kq + 0][2 * a_m]) = make_float2(v.x, v.x);
        *reinterpret_cast<float2*>(&As2[0][a_kq + 1][2 * a_m]) = make_float2(v.y, v.y);
        *reinterpret_cast<float2*>(&As2[0][a_kq + 2][2 * a_m]) = make_float2(v.z, v.z);
        *reinterpret_cast<float2*>(&As2[0][a_kq + 3][2 * a_m]) = make_float2(v.w, v.w);
    }
#pragma unroll
    for (int kg = 0; kg < 4; kg++) {
        float4 v = *reinterpret_cast<const float4*>(&Brow[kg * 4]);
        Bs[0][kg * 4 + 0][t] = v.x; Bs[0][kg * 4 + 1][t] = v.y;
        Bs[0][kg * 4 + 2][t] = v.z; Bs[0][kg * 4 + 3][t] = v.w;
    }
    __syncthreads();

#pragma unroll
    for (int it = 0; it < NT; it++) {
        const int buf = it & 1;
        // issue next tile's loads into the other buffer (overlaps with compute)
        if (it + 1 < NT) {
            const int nb = buf ^ 1;
            const int k1 = (it + 1) * BK;
            if (t < 128) {
                float4 v = *reinterpret_cast<const float4*>(&Arow[k1]);
                *reinterpret_cast<float2*>(&As2[nb][a_kq + 0][2 * a_m]) = make_float2(v.x, v.x);
                *reinterpret_cast<float2*>(&As2[nb][a_kq + 1][2 * a_m]) = make_float2(v.y, v.y);
                *reinterpret_cast<float2*>(&As2[nb][a_kq + 2][2 * a_m]) = make_float2(v.z, v.z);
                *reinterpret_cast<float2*>(&As2[nb][a_kq + 3][2 * a_m]) = make_float2(v.w, v.w);
            }
#pragma unroll
            for (int kg = 0; kg < 4; kg++) {
                float4 v = *reinterpret_cast<const float4*>(&Brow[k1 + kg * 4]);
                Bs[nb][kg * 4 + 0][t] = v.x; Bs[nb][kg * 4 + 1][t] = v.y;
                Bs[nb][kg * 4 + 2][t] = v.z; Bs[nb][kg * 4 + 3][t] = v.w;
            }
        }
        // compute on current buffer
#pragma unroll
        for (int kk = 0; kk < BK; kk++) {
            // A duplicated pairs: 8 contiguous floats = 2 LDS.128, warp-broadcast
            ulonglong2 a01 = *reinterpret_cast<const ulonglong2*>(&As2[buf][kk][trow * 8]);
            ulonglong2 a23 = *reinterpret_cast<const ulonglong2*>(&As2[buf][kk][trow * 8 + 4]);
            u64 aa[4] = {a01.x, a01.y, a23.x, a23.y};
            ulonglong2 b01 = *reinterpret_cast<const ulonglong2*>(&Bs[buf][kk][tcol * 4]);
            ulonglong2 b23 = *reinterpret_cast<const ulonglong2*>(&Bs[buf][kk][128 + tcol * 4]);
            u64 bb[4] = {b01.x, b01.y, b23.x, b23.y};
#pragma unroll
            for (int r = 0; r < 4; r++)
#pragma unroll
                for (int p = 0; p < 4; p++) fma2(acc2[r][p], aa[r], bb[p]);
        }
        // single barrier: publishes buf^1 writes, protects buf for next overwrite
        __syncthreads();
    }

    const int c0 = tcol * 4;
    const int c1 = 128 + tcol * 4;

    float acc[4][8];
#pragma unroll
    for (int r = 0; r < 4; r++)
#pragma unroll
        for (int p = 0; p < 4; p++) unpack2(acc2[r][p], acc[r][2 * p], acc[r][2 * p + 1]);

    if (EPI == 0) {
#pragma unroll
        for (int r = 0; r < 4; r++) {
            int m = m0 + trow * 4 + r;
            *reinterpret_cast<float4*>(&C[m * HID + c0]) = make_float4(acc[r][0], acc[r][1], acc[r][2], acc[r][3]);
            *reinterpret_cast<float4*>(&C[m * HID + c1]) = make_float4(acc[r][4], acc[r][5], acc[r][6], acc[r][7]);
        }
    } else if (EPI == 1) {
        float4 bi0 = *reinterpret_cast<const float4*>(&bias[c0]);
        float4 bi1 = *reinterpret_cast<const float4*>(&bias[c1]);
        float bb[8] = {bi0.x, bi0.y, bi0.z, bi0.w, bi1.x, bi1.y, bi1.z, bi1.w};
#pragma unroll
        for (int r = 0; r < 4; r++) {
            int m = m0 + trow * 4 + r;
            float o[8];
#pragma unroll
            for (int j = 0; j < 8; j++) o[j] = fmaxf(acc[r][j] + bb[j], 0.f);
            *reinterpret_cast<float4*>(&C[m * HID + c0]) = make_float4(o[0], o[1], o[2], o[3]);
            *reinterpret_cast<float4*>(&C[m * HID + c1]) = make_float4(o[4], o[5], o[6], o[7]);
        }
    } else {
        float4 bi0 = *reinterpret_cast<const float4*>(&bias[c0]);
        float4 bi1 = *reinterpret_cast<const float4*>(&bias[c1]);
        float4 g0  = *reinterpret_cast<const float4*>(&gamma[c0]);
        float4 g1  = *reinterpret_cast<const float4*>(&gamma[c1]);
        float4 be0 = *reinterpret_cast<const float4*>(&beta[c0]);
        float4 be1 = *reinterpret_cast<const float4*>(&beta[c1]);
        float bb[8]  = {bi0.x, bi0.y, bi0.z, bi0.w, bi1.x, bi1.y, bi1.z, bi1.w};
        float gg[8]  = {g0.x, g0.y, g0.z, g0.w, g1.x, g1.y, g1.z, g1.w};
        float bt[8]  = {be0.x, be0.y, be0.z, be0.w, be1.x, be1.y, be1.z, be1.w};
#pragma unroll
        for (int r = 0; r < 4; r++) {
            int m = m0 + trow * 4 + r;
            float4 h0 = *reinterpret_cast<const float4*>(&resid[m * HID + c0]);
            float4 h1 = *reinterpret_cast<const float4*>(&resid[m * HID + c1]);
            float hv[8] = {h0.x, h0.y, h0.z, h0.w, h1.x, h1.y, h1.z, h1.w};
            float z[8];
            float s = 0.f, q = 0.f;
#pragma unroll
            for (int j = 0; j < 8; j++) {
                z[j] = acc[r][j] + bb[j] + hv[j];
                s += z[j];
                q = fmaf(z[j], z[j], q);
            }
            // each C row lives entirely in one warp -> warp allreduce
#pragma unroll
            for (int off = 16; off > 0; off >>= 1) {
                s += __shfl_xor_sync(0xffffffffu, s, off);
                q += __shfl_xor_sync(0xffffffffu, q, off);
            }
            float mu  = s * (1.f / HID);
            float var = q * (1.f / HID) - mu * mu;
            float rsd = rsqrtf(var + LN_EPS);
            float o[8];
#pragma unroll
            for (int j = 0; j < 8; j++)
                o[j] = fmaf(gg[j] * (z[j] - mu), rsd, bt[j]);
            *reinterpret_cast<float4*>(&C[m * HID + c0]) = make_float4(o[0], o[1], o[2], o[3]);
            *reinterpret_cast<float4*>(&C[m * HID + c1]) = make_float4(o[4], o[5], o[6], o[7]);
        }
    }
}

// ---------------- pair head (tiny MLP), single block ----------------
__global__ void head_kernel(const float* __restrict__ W1, const float* __restrict__ b1,
                            const float* __restrict__ W2, const float* __restrict__ b2,
                            const float* __restrict__ W3, const float* __restrict__ b3,
                            float* __restrict__ out, int out_size) {
    __shared__ float feat[4 * HID];
    __shared__ float h1[2 * HID];
    __shared__ float h2[HID];
    const int t = threadIdx.x;       // 256
    const float inv = 1.f / (float)N_NODES;
    {
        // deterministic fixed-order reduction of column partials
        float ea = 0.f, eb = 0.f;
        for (int i = 0; i < NPART; i++) {
            ea += g_part[i * HID + t];
            eb += g_part[(NPART + i) * HID + t];
        }
        ea *= inv; eb *= inv;
        feat[t]           = ea;
        feat[HID + t]     = eb;
        feat[2 * HID + t] = fabsf(ea - eb);
        feat[3 * HID + t] = ea * eb;
        if (out_size >= 513) {
            out[1 + t]       = ea;
            out[1 + HID + t] = eb;
        }
    }
    __syncthreads();
    const int w = t >> 5, lane = t & 31;
    for (int o = w; o < 2 * HID; o += 8) {
        const float* row = W1 + o * (4 * HID);
        float s = 0.f;
        for (int k = lane * 4; k < 4 * HID; k += 128) {
            float4 v = *reinterpret_cast<const float4*>(&row[k]);
            float4 f = *reinterpret_cast<const float4*>(&feat[k]);
            s += v.x * f.x + v.y * f.y + v.z * f.z + v.w * f.w;
        }
#pragma unroll
        for (int off = 16; off > 0; off >>= 1) s += __shfl_xor_sync(0xffffffffu, s, off);
        if (lane == 0) h1[o] = fmaxf(s + b1[o], 0.f);
    }
    __syncthreads();
    for (int o = w; o < HID; o += 8) {
        const float* row = W2 + o * (2 * HID);
        float s = 0.f;
        for (int k = lane * 4; k < 2 * HID; k += 128) {
            float4 v = *reinterpret_cast<const float4*>(&row[k]);
            float4 f = *reinterpret_cast<const float4*>(&h1[k]);
            s += v.x * f.x + v.y * f.y + v.z * f.z + v.w * f.w;
        }
#pragma unroll
        for (int off = 16; off > 0; off >>= 1) s += __shfl_xor_sync(0xffffffffu, s, off);
        if (lane == 0) h2[o] = fmaxf(s + b2[o], 0.f);
    }
    __syncthreads();
    if (w == 0) {
        float s = 0.f;
        for (int k = lane * 4; k < HID; k += 128) {
            float4 v = *reinterpret_cast<const float4*>(&W3[k]);
            float4 f = *reinterpret_cast<const float4*>(&h2[k]);
            s += v.x * f.x + v.y * f.y + v.z * f.z + v.w * f.w;
        }
#pragma unroll
        for (int off = 16; off > 0; off >>= 1) s += __shfl_xor_sync(0xffffffffu, s, off);
        if (lane == 0) out[0] = s + b3[0];
    }
}

// ---------------- host ----------------
extern "C" void kernel_launch(void* const* d_in, const int* in_sizes, int n_in,
                              void* d_out, int out_size) {
    const float* x_a  = (const float*)d_in[0];
    const int*   ei_a = (const int*)  d_in[1];
    const int*   et_a = (const int*)  d_in[2];
    const float* x_b  = (const float*)d_in[3];
    const int*   ei_b = (const int*)  d_in[4];
    const int*   et_b = (const int*)  d_in[5];
    const float* W_in = (const float*)d_in[6];
    const float* b_in = (const float*)d_in[7];
    const float* eemb = (const float*)d_in[8];
    const float* Wmsg = (const float*)d_in[9];
    const float* bmsg = (const float*)d_in[10];
    const float* Wupd = (const float*)d_in[11];
    const float* bupd = (const float*)d_in[12];
    const float* lng  = (const float*)d_in[13];
    const float* lnb  = (const float*)d_in[14];
    const float* W1   = (const float*)d_in[15];
    const float* b1   = (const float*)d_in[16];
    const float* W2   = (const float*)d_in[17];
    const float* b2   = (const float*)d_in[18];
    const float* W3   = (const float*)d_in[19];
    const float* b3   = (const float*)d_in[20];
    float* out = (float*)d_out;

    const int* src_a = ei_a;
    const int* dst_a = ei_a + N_EDGES;
    const int* src_b = ei_b;
    const int* dst_b = ei_b + N_EDGES;

    float *hptr, *Hmptr, *aggptr;
    cudaGetSymbolAddress((void**)&hptr,   g_h);
    cudaGetSymbolAddress((void**)&Hmptr,  g_Hm);
    cudaGetSymbolAddress((void**)&aggptr, g_agg);

    const int GEMM_GRID = N_TOT / 32;            // 1250
    const int EGRID     = (E_TOT + 255) / 256;   // 2500

    etb_kernel<<<(NL * NUM_ET * HID + 255) / 256, 256>>>(eemb, Wmsg, bmsg);

    // merged CSR build (both graphs, shared across layers)
    zero_counts_kernel<<<(N_TOT + 255) / 256, 256>>>();
    hist_kernel<<<EGRID, 256>>>(dst_a, dst_b);
    scan_kernel<<<1, 1024>>>();
    scatter_kernel<<<EGRID, 256>>>(src_a, dst_a, et_a, src_b, dst_b, et_b);

    // encoder: h = relu(x @ W_in^T + b_in), both graphs in one launch
    gemm_kernel<IN_DIM, 1><<<GEMM_GRID, 256>>>(x_a, x_b, N_NODES, IN_DIM,
                                               W_in, IN_DIM,
                                               b_in, nullptr, nullptr, nullptr, hptr);

    for (int l = 0; l < NL; l++) {
        // Hm = h @ Wh^T   (Wh = W_msg[l][:, :256], row stride 288)
        gemm_kernel<HID, 0><<<GEMM_GRID, 256>>>(hptr, hptr + (size_t)N_NODES * HID, N_NODES, HID,
                                                Wmsg + l * HID * (HID + ETD), HID + ETD,
                                                nullptr, nullptr, nullptr, nullptr, Hmptr);
        // agg = segment-mean of relu(Hm[src] + etb[et]) over in-edges
        agg_kernel<<<N_TOT, HID / 4>>>(l);
        // h = LN(h + agg @ W_upd^T + b_upd)
        gemm_kernel<HID, 2><<<GEMM_GRID, 256>>>(aggptr, aggptr + (size_t)N_NODES * HID, N_NODES, HID,
                                                Wupd + l * HID * HID, HID,
                                                bupd + l * HID, hptr,
                                                lng + l * HID, lnb + l * HID, hptr);
    }

    colmean_kernel<<<2 * NPART, 256>>>();
    head_kernel<<<1, 256>>>(W1, b1, W2, b2, W3, b3, out, out_size);
}

// round 16
// speedup vs baseline: 1.2215x; 1.2215x over previous
#include <cuda_runtime.h>

#define N_NODES 20000
#define N_TOT   40000            // both graphs merged
#define N_EDGES 320000
#define E_TOT   640000
#define IN_DIM  128
#define HID     256
#define NL      3
#define NUM_ET  16
#define ETD     32
#define LN_EPS  1e-5f
#define NPART   100              // partials per graph for column mean
#define ETB_N   (NL * NUM_ET * HID)

typedef unsigned long long u64;

// ---------------- scratch (device globals; no allocation allowed) ----------------
__device__ float g_h  [N_TOT * HID];
__device__ float g_Hm [N_TOT * HID];
__device__ float g_agg[N_TOT * HID];
__device__ int   g_cnt[N_TOT];
__device__ int   g_cur[N_TOT];
__device__ int   g_rs [N_TOT + 1];
__device__ int   g_csrc[E_TOT];
__device__ int   g_cet [E_TOT];
__device__ float g_etb [ETB_N];
__device__ float g_part[2 * NPART * HID];

// ---------------- f32x2 packed-math helpers (sm_10x) ----------------
__device__ __forceinline__ void unpack2(u64 v, float& x, float& y) {
    asm("mov.b64 {%0, %1}, %2;" : "=f"(x), "=f"(y) : "l"(v));
}
__device__ __forceinline__ void fma2(u64& d, u64 a, u64 b) {
    asm("fma.rn.f32x2 %0, %1, %2, %0;" : "+l"(d) : "l"(a), "l"(b));
}

// ---------------- prep: etb table + zero CSR counters (merged) ----------------
// etb[l][t][o] = edge_embs[l][t] @ We[l]^T + b_msg[l]
__global__ void prep_kernel(const float* __restrict__ eemb,
                            const float* __restrict__ Wmsg,
                            const float* __restrict__ bmsg) {
    int idx = blockIdx.x * blockDim.x + threadIdx.x;
    if (idx < ETB_N) {
        int o = idx % HID;
        int t = (idx / HID) % NUM_ET;
        int l = idx / (HID * NUM_ET);
        const float* e = eemb + (l * NUM_ET + t) * ETD;
        const float* w = Wmsg + (l * HID + o) * (HID + ETD) + HID;
        float s = bmsg[l * HID + o];
#pragma unroll
        for (int j = 0; j < ETD; j++) s = fmaf(e[j], w[j], s);
        g_etb[idx] = s;
    } else {
        int i = idx - ETB_N;
        if (i < N_TOT) { g_cnt[i] = 0; g_cur[i] = 0; }
    }
}

__global__ void hist_kernel(const int* __restrict__ dst_a,
                            const int* __restrict__ dst_b) {
    int e = blockIdx.x * blockDim.x + threadIdx.x;
    if (e >= E_TOT) return;
    int d = (e < N_EDGES) ? dst_a[e] : (dst_b[e - N_EDGES] + N_NODES);
    atomicAdd(&g_cnt[d], 1);
}

// single-block exclusive scan over 40000 counts (int4 loads: 40000 = 1000*40)
__global__ void scan_kernel() {
    __shared__ int ps[1024];
    const int t = threadIdx.x;
    const int C = (N_TOT + 1023) / 1024;   // 40
    int base = t * C;
    int s = 0;
    int vals[40];
    if (base < N_TOT) {
#pragma unroll
        for (int q = 0; q < C / 4; q++) {
            int4 v = *reinterpret_cast<const int4*>(&g_cnt[base + q * 4]);
            vals[q * 4 + 0] = v.x; vals[q * 4 + 1] = v.y;
            vals[q * 4 + 2] = v.z; vals[q * 4 + 3] = v.w;
            s += v.x + v.y + v.z + v.w;
        }
    }
    ps[t] = s;
    __syncthreads();
    for (int off = 1; off < 1024; off <<= 1) {
        int v = (t >= off) ? ps[t - off] : 0;
        __syncthreads();
        ps[t] += v;
        __syncthreads();
    }
    if (base < N_TOT) {
        int run = (t > 0) ? ps[t - 1] : 0;
#pragma unroll
        for (int i = 0; i < C; i++) { g_rs[base + i] = run; run += vals[i]; }
    }
    if (t == 1023) g_rs[N_TOT] = ps[1023];
}

__global__ void scatter_kernel(const int* __restrict__ src_a,
                               const int* __restrict__ dst_a,
                               const int* __restrict__ et_a,
                               const int* __restrict__ src_b,
                               const int* __restrict__ dst_b,
                               const int* __restrict__ et_b) {
    int e = blockIdx.x * blockDim.x + threadIdx.x;
    if (e >= E_TOT) return;
    int s, d, t;
    if (e < N_EDGES) {
        s = src_a[e];            d = dst_a[e];            t = et_a[e];
    } else {
        int eb = e - N_EDGES;
        s = src_b[eb] + N_NODES; d = dst_b[eb] + N_NODES; t = et_b[eb];
    }
    int p = g_rs[d] + atomicAdd(&g_cur[d], 1);
    g_csrc[p] = s;
    g_cet[p]  = t;
}

// ---------------- edge aggregation (gather-style, float4, no atomics) --------
__global__ void agg_kernel(int layer) {
    int n  = blockIdx.x;
    int c4 = threadIdx.x;                               // 0..63
    const float4* __restrict__ Hm4  = (const float4*)g_Hm;
    const float4* __restrict__ et4  = (const float4*)(g_etb + layer * NUM_ET * HID);
    int beg = g_rs[n], end = g_rs[n + 1];
    float4 acc = make_float4(0.f, 0.f, 0.f, 0.f);
    for (int i = beg; i < end; i++) {
        int s = g_csrc[i];
        int t = g_cet[i];
        float4 hv = Hm4[s * (HID / 4) + c4];
        float4 ev = __ldg(&et4[t * (HID / 4) + c4]);
        acc.x += fmaxf(hv.x + ev.x, 0.f);
        acc.y += fmaxf(hv.y + ev.y, 0.f);
        acc.z += fmaxf(hv.z + ev.z, 0.f);
        acc.w += fmaxf(hv.w + ev.w, 0.f);
    }
    float inv = 1.f / fmaxf((float)(end - beg), 1.f);
    acc.x *= inv; acc.y *= inv; acc.z *= inv; acc.w *= inv;
    ((float4*)g_agg)[n * (HID / 4) + c4] = acc;
}

// ---------------- column-mean partials (both graphs, deterministic) ----------
__global__ void colmean_kernel() {
    int c = threadIdx.x;                    // 256
    const int rows_per = N_TOT / (2 * NPART);   // 200
    int r0 = blockIdx.x * rows_per;
    int r1 = r0 + rows_per;
    float acc = 0.f;
    for (int r = r0; r < r1; r++) acc += g_h[r * HID + c];
    g_part[blockIdx.x * HID + c] = acc;
}

// ---------------- fused GEMM: C[M,256] = A[M,K] @ B[256,K]^T (+ epilogue) ----
// BM=64 block tile, 8x8 register tile, double-buffered smem, 1 barrier/tile.
// A stored DUPLICATED in smem (As2[k][2m]=As2[k][2m+1]=A[m][k]) so (a,a) f32x2
// operands come straight from broadcast LDS. Per-thread A-row pointer select
// handles the graph a/b split even for straddling blocks.
// EPI 0: C = acc ; EPI 1: relu(acc+bias) ; EPI 2: LN(acc+bias+resid)
template <int KDIM, int EPI>
__global__ void __launch_bounds__(256, 2)
gemm_kernel(const float* __restrict__ A_a, const float* __restrict__ A_b,
            int asplit, int lda,
            const float* __restrict__ B, int ldb,
            const float* __restrict__ bias,
            const float* __restrict__ resid,
            const float* __restrict__ gamma,
            const float* __restrict__ beta,
            float* __restrict__ C) {
    constexpr int BM = 64, BK = 16;
    constexpr int NT = KDIM / BK;
    __shared__ float As2[2][BK][BM * 2];   // 16 KB, duplicated pairs
    __shared__ float Bs [2][BK][256];      // 32 KB

    const int t    = threadIdx.x;
    const int tcol = t & 31;
    const int trow = t >> 5;               // warp id: 8 row-groups of 8 rows
    const int m0   = blockIdx.x * BM;

    // A load mapping: all 256 threads, one float4 each (64 rows x 16 cols)
    const int a_m  = t >> 2;               // 0..63
    const int a_kq = (t & 3) * 4;
    const int grow = m0 + a_m;
    const float* Arow = ((grow < asplit) ? A_a + (size_t)grow * lda
                                         : A_b + (size_t)(grow - asplit) * lda) + a_kq;
    const float* Brow = &B[t * ldb];

    u64 acc2[8][4];
#pragma unroll
    for (int r = 0; r < 8; r++)
#pragma unroll
        for (int p = 0; p < 4; p++) acc2[r][p] = 0ull;

    // ---- prologue: tile 0 ----
    {
        float4 v = *reinterpret_cast<const float4*>(Arow);
        *reinterpret_cast<float2*>(&As2[0][a_kq + 0][2 * a_m]) = make_float2(v.x, v.x);
        *reinterpret_cast<float2*>(&As2[0][a_kq + 1][2 * a_m]) = make_float2(v.y, v.y);
        *reinterpret_cast<float2*>(&As2[0][a_kq + 2][2 * a_m]) = make_float2(v.z, v.z);
        *reinterpret_cast<float2*>(&As2[0][a_kq + 3][2 * a_m]) = make_float2(v.w, v.w);
    }
#pragma unroll
    for (int kg = 0; kg < 4; kg++) {
        float4 v = *reinterpret_cast<const float4*>(&Brow[kg * 4]);
        Bs[0][kg * 4 + 0][t] = v.x; Bs[0][kg * 4 + 1][t] = v.y;
        Bs[0][kg * 4 + 2][t] = v.z; Bs[0][kg * 4 + 3][t] = v.w;
    }
    __syncthreads();

#pragma unroll
    for (int it = 0; it < NT; it++) {
        const int buf = it & 1;
        if (it + 1 < NT) {
            const int nb = buf ^ 1;
            const int k1 = (it + 1) * BK;
            float4 v = *reinterpret_cast<const float4*>(&Arow[k1]);
            *reinterpret_cast<float2*>(&As2[nb][a_kq + 0][2 * a_m]) = make_float2(v.x, v.x);
            *reinterpret_cast<float2*>(&As2[nb][a_kq + 1][2 * a_m]) = make_float2(v.y, v.y);
            *reinterpret_cast<float2*>(&As2[nb][a_kq + 2][2 * a_m]) = make_float2(v.z, v.z);
            *reinterpret_cast<float2*>(&As2[nb][a_kq + 3][2 * a_m]) = make_float2(v.w, v.w);
#pragma unroll
            for (int kg = 0; kg < 4; kg++) {
                float4 w = *reinterpret_cast<const float4*>(&Brow[k1 + kg * 4]);
                Bs[nb][kg * 4 + 0][t] = w.x; Bs[nb][kg * 4 + 1][t] = w.y;
                Bs[nb][kg * 4 + 2][t] = w.z; Bs[nb][kg * 4 + 3][t] = w.w;
            }
        }
#pragma unroll
        for (int kk = 0; kk < BK; kk++) {
            // A: 8 duplicated pairs = 16 contiguous floats, warp-broadcast
            ulonglong2 a01 = *reinterpret_cast<const ulonglong2*>(&As2[buf][kk][trow * 16]);
            ulonglong2 a23 = *reinterpret_cast<const ulonglong2*>(&As2[buf][kk][trow * 16 + 4]);
            ulonglong2 a45 = *reinterpret_cast<const ulonglong2*>(&As2[buf][kk][trow * 16 + 8]);
            ulonglong2 a67 = *reinterpret_cast<const ulonglong2*>(&As2[buf][kk][trow * 16 + 12]);
            u64 aa[8] = {a01.x, a01.y, a23.x, a23.y, a45.x, a45.y, a67.x, a67.y};
            ulonglong2 b01 = *reinterpret_cast<const ulonglong2*>(&Bs[buf][kk][tcol * 4]);
            ulonglong2 b23 = *reinterpret_cast<const ulonglong2*>(&Bs[buf][kk][128 + tcol * 4]);
            u64 bb[4] = {b01.x, b01.y, b23.x, b23.y};
#pragma unroll
            for (int r = 0; r < 8; r++)
#pragma unroll
                for (int p = 0; p < 4; p++) fma2(acc2[r][p], aa[r], bb[p]);
        }
        __syncthreads();
    }

    const int c0 = tcol * 4;
    const int c1 = 128 + tcol * 4;

    if (EPI == 0) {
#pragma unroll
        for (int r = 0; r < 8; r++) {
            int m = m0 + trow * 8 + r;
            float a0, a1, a2, a3, a4, a5, a6, a7;
            unpack2(acc2[r][0], a0, a1); unpack2(acc2[r][1], a2, a3);
            unpack2(acc2[r][2], a4, a5); unpack2(acc2[r][3], a6, a7);
            *reinterpret_cast<float4*>(&C[m * HID + c0]) = make_float4(a0, a1, a2, a3);
            *reinterpret_cast<float4*>(&C[m * HID + c1]) = make_float4(a4, a5, a6, a7);
        }
    } else if (EPI == 1) {
        float4 bi0 = *reinterpret_cast<const float4*>(&bias[c0]);
        float4 bi1 = *reinterpret_cast<const float4*>(&bias[c1]);
        float bb[8] = {bi0.x, bi0.y, bi0.z, bi0.w, bi1.x, bi1.y, bi1.z, bi1.w};
#pragma unroll
        for (int r = 0; r < 8; r++) {
            int m = m0 + trow * 8 + r;
            float a[8];
            unpack2(acc2[r][0], a[0], a[1]); unpack2(acc2[r][1], a[2], a[3]);
            unpack2(acc2[r][2], a[4], a[5]); unpack2(acc2[r][3], a[6], a[7]);
            float o[8];
#pragma unroll
            for (int j = 0; j < 8; j++) o[j] = fmaxf(a[j] + bb[j], 0.f);
            *reinterpret_cast<float4*>(&C[m * HID + c0]) = make_float4(o[0], o[1], o[2], o[3]);
            *reinterpret_cast<float4*>(&C[m * HID + c1]) = make_float4(o[4], o[5], o[6], o[7]);
        }
    } else {
        float4 bi0 = *reinterpret_cast<const float4*>(&bias[c0]);
        float4 bi1 = *reinterpret_cast<const float4*>(&bias[c1]);
        float4 g0  = *reinterpret_cast<const float4*>(&gamma[c0]);
        float4 g1  = *reinterpret_cast<const float4*>(&gamma[c1]);
        float4 be0 = *reinterpret_cast<const float4*>(&beta[c0]);
        float4 be1 = *reinterpret_cast<const float4*>(&beta[c1]);
        float bb[8]  = {bi0.x, bi0.y, bi0.z, bi0.w, bi1.x, bi1.y, bi1.z, bi1.w};
        float gg[8]  = {g0.x, g0.y, g0.z, g0.w, g1.x, g1.y, g1.z, g1.w};
        float bt[8]  = {be0.x, be0.y, be0.z, be0.w, be1.x, be1.y, be1.z, be1.w};
#pragma unroll
        for (int r = 0; r < 8; r++) {
            int m = m0 + trow * 8 + r;
            float a[8];
            unpack2(acc2[r][0], a[0], a[1]); unpack2(acc2[r][1], a[2], a[3]);
            unpack2(acc2[r][2], a[4], a[5]); unpack2(acc2[r][3], a[6], a[7]);
            float4 h0 = *reinterpret_cast<const float4*>(&resid[m * HID + c0]);
            float4 h1 = *reinterpret_cast<const float4*>(&resid[m * HID + c1]);
            float hv[8] = {h0.x, h0.y, h0.z, h0.w, h1.x, h1.y, h1.z, h1.w};
            float z[8];
            float s = 0.f, q = 0.f;
#pragma unroll
            for (int j = 0; j < 8; j++) {
                z[j] = a[j] + bb[j] + hv[j];
                s += z[j];
                q = fmaf(z[j], z[j], q);
            }
            // each C row lives entirely in one warp -> warp allreduce
#pragma unroll
            for (int off = 16; off > 0; off >>= 1) {
                s += __shfl_xor_sync(0xffffffffu, s, off);
                q += __shfl_xor_sync(0xffffffffu, q, off);
            }
            float mu  = s * (1.f / HID);
            float var = q * (1.f / HID) - mu * mu;
            float rsd = rsqrtf(var + LN_EPS);
            float o[8];
#pragma unroll
            for (int j = 0; j < 8; j++)
                o[j] = fmaf(gg[j] * (z[j] - mu), rsd, bt[j]);
            *reinterpret_cast<float4*>(&C[m * HID + c0]) = make_float4(o[0], o[1], o[2], o[3]);
            *reinterpret_cast<float4*>(&C[m * HID + c1]) = make_float4(o[4], o[5], o[6], o[7]);
        }
    }
}

// ---------------- pair head (tiny MLP), single block ----------------
__global__ void head_kernel(const float* __restrict__ W1, const float* __restrict__ b1,
                            const float* __restrict__ W2, const float* __restrict__ b2,
                            const float* __restrict__ W3, const float* __restrict__ b3,
                            float* __restrict__ out, int out_size) {
    __shared__ float feat[4 * HID];
    __shared__ float h1[2 * HID];
    __shared__ float h2[HID];
    const int t = threadIdx.x;       // 256
    const float inv = 1.f / (float)N_NODES;
    {
        float ea = 0.f, eb = 0.f;
        for (int i = 0; i < NPART; i++) {
            ea += g_part[i * HID + t];
            eb += g_part[(NPART + i) * HID + t];
        }
        ea *= inv; eb *= inv;
        feat[t]           = ea;
        feat[HID + t]     = eb;
        feat[2 * HID + t] = fabsf(ea - eb);
        feat[3 * HID + t] = ea * eb;
        if (out_size >= 513) {
            out[1 + t]       = ea;
            out[1 + HID + t] = eb;
        }
    }
    __syncthreads();
    const int w = t >> 5, lane = t & 31;
    for (int o = w; o < 2 * HID; o += 8) {
        const float* row = W1 + o * (4 * HID);
        float s = 0.f;
        for (int k = lane * 4; k < 4 * HID; k += 128) {
            float4 v = *reinterpret_cast<const float4*>(&row[k]);
            float4 f = *reinterpret_cast<const float4*>(&feat[k]);
            s += v.x * f.x + v.y * f.y + v.z * f.z + v.w * f.w;
        }
#pragma unroll
        for (int off = 16; off > 0; off >>= 1) s += __shfl_xor_sync(0xffffffffu, s, off);
        if (lane == 0) h1[o] = fmaxf(s + b1[o], 0.f);
    }
    __syncthreads();
    for (int o = w; o < HID; o += 8) {
        const float* row = W2 + o * (2 * HID);
        float s = 0.f;
        for (int k = lane * 4; k < 2 * HID; k += 128) {
            float4 v = *reinterpret_cast<const float4*>(&row[k]);
            float4 f = *reinterpret_cast<const float4*>(&h1[k]);
            s += v.x * f.x + v.y * f.y + v.z * f.z + v.w * f.w;
        }
#pragma unroll
        for (int off = 16; off > 0; off >>= 1) s += __shfl_xor_sync(0xffffffffu, s, off);
        if (lane == 0) h2[o] = fmaxf(s + b2[o], 0.f);
    }
    __syncthreads();
    if (w == 0) {
        float s = 0.f;
        for (int k = lane * 4; k < HID; k += 128) {
            float4 v = *reinterpret_cast<const float4*>(&W3[k]);
            float4 f = *reinterpret_cast<const float4*>(&h2[k]);
            s += v.x * f.x + v.y * f.y + v.z * f.z + v.w * f.w;
        }
#pragma unroll
        for (int off = 16; off > 0; off >>= 1) s += __shfl_xor_sync(0xffffffffu, s, off);
        if (lane == 0) out[0] = s + b3[0];
    }
}

// ---------------- host ----------------
extern "C" void kernel_launch(void* const* d_in, const int* in_sizes, int n_in,
                              void* d_out, int out_size) {
    const float* x_a  = (const float*)d_in[0];
    const int*   ei_a = (const int*)  d_in[1];
    const int*   et_a = (const int*)  d_in[2];
    const float* x_b  = (const float*)d_in[3];
    const int*   ei_b = (const int*)  d_in[4];
    const int*   et_b = (const int*)  d_in[5];
    const float* W_in = (const float*)d_in[6];
    const float* b_in = (const float*)d_in[7];
    const float* eemb = (const float*)d_in[8];
    const float* Wmsg = (const float*)d_in[9];
    const float* bmsg = (const float*)d_in[10];
    const float* Wupd = (const float*)d_in[11];
    const float* bupd = (const float*)d_in[12];
    const float* lng  = (const float*)d_in[13];
    const float* lnb  = (const float*)d_in[14];
    const float* W1   = (const float*)d_in[15];
    const float* b1   = (const float*)d_in[16];
    const float* W2   = (const float*)d_in[17];
    const float* b2   = (const float*)d_in[18];
    const float* W3   = (const float*)d_in[19];
    const float* b3   = (const float*)d_in[20];
    float* out = (float*)d_out;

    const int* src_a = ei_a;
    const int* dst_a = ei_a + N_EDGES;
    const int* src_b = ei_b;
    const int* dst_b = ei_b + N_EDGES;

    float *hptr, *Hmptr, *aggptr;
    cudaGetSymbolAddress((void**)&hptr,   g_h);
    cudaGetSymbolAddress((void**)&Hmptr,  g_Hm);
    cudaGetSymbolAddress((void**)&aggptr, g_agg);

    const int GEMM_GRID = N_TOT / 64;            // 625
    const int EGRID     = (E_TOT + 255) / 256;   // 2500

    // prep: etb table + zero CSR counters (one launch)
    prep_kernel<<<(ETB_N + N_TOT + 255) / 256, 256>>>(eemb, Wmsg, bmsg);
    hist_kernel<<<EGRID, 256>>>(dst_a, dst_b);
    scan_kernel<<<1, 1024>>>();
    scatter_kernel<<<EGRID, 256>>>(src_a, dst_a, et_a, src_b, dst_b, et_b);

    // encoder: h = relu(x @ W_in^T + b_in), both graphs in one launch
    gemm_kernel<IN_DIM, 1><<<GEMM_GRID, 256>>>(x_a, x_b, N_NODES, IN_DIM,
                                               W_in, IN_DIM,
                                               b_in, nullptr, nullptr, nullptr, hptr);

    for (int l = 0; l < NL; l++) {
        // Hm = h @ Wh^T   (Wh = W_msg[l][:, :256], row stride 288)
        gemm_kernel<HID, 0><<<GEMM_GRID, 256>>>(hptr, hptr + (size_t)N_NODES * HID, N_NODES, HID,
                                                Wmsg + l * HID * (HID + ETD), HID + ETD,
                                                nullptr, nullptr, nullptr, nullptr, Hmptr);
        // agg = segment-mean of relu(Hm[src] + etb[et]) over in-edges
        agg_kernel<<<N_TOT, HID / 4>>>(l);
        // h = LN(h + agg @ W_upd^T + b_upd)
        gemm_kernel<HID, 2><<<GEMM_GRID, 256>>>(aggptr, aggptr + (size_t)N_NODES * HID, N_NODES, HID,
                                                Wupd + l * HID * HID, HID,
                                                bupd + l * HID, hptr,
                                                lng + l * HID, lnb + l * HID, hptr);
    }

    colmean_kernel<<<2 * NPART, 256>>>();
    head_kernel<<<1, 256>>>(W1, b1, W2, b2, W3, b3, out, out_size);
}